// round 6
// baseline (speedup 1.0000x reference)
#include <cuda_runtime.h>

#define NSEQ  2048
#define DMODEL 768
#define NH    12
#define DH    64
#define BATCH 2
#define MROWS 4096          // BATCH*NSEQ
#define S3DIM 2304          // 3*DMODEL
#define SCALE 0.125f        // DH^-0.5
#define NBH   (BATCH*NH)    // 24

// Scratch (tf32 bit patterns stored as unsigned)
__device__ unsigned g_q[BATCH*NH*NSEQ*DH];   // [bh][n][dh] row-major
__device__ unsigned g_k[BATCH*NH*NSEQ*DH];
__device__ unsigned g_v[BATCH*NH*NSEQ*DH];
__device__ unsigned g_att[MROWS*DMODEL];

// Fragment-packed layouts
__device__ uint4 g_qp[NBH*128*8*32];   // [bh][qb(16-row blk)][d8][lane] A-frag
__device__ uint2 g_kp[NBH*256*8*32];   // [bh][jb(8-row blk)][d8][lane]  B-frag (QK^T)
__device__ uint2 g_vp[NBH*256*8*32];   // [bh][vb(8-row blk)][jdh][lane] B-frag (PV)

__device__ __forceinline__ unsigned f2t(float f){
    unsigned u; asm("cvt.rna.tf32.f32 %0, %1;" : "=r"(u) : "f"(f)); return u;
}
__device__ __forceinline__ void mma_tf32(float c[4], const unsigned a[4], const unsigned b[2]){
    asm volatile("mma.sync.aligned.m16n8k8.row.col.f32.tf32.tf32.f32 "
        "{%0,%1,%2,%3}, {%4,%5,%6,%7}, {%8,%9}, {%0,%1,%2,%3};"
        : "+f"(c[0]), "+f"(c[1]), "+f"(c[2]), "+f"(c[3])
        : "r"(a[0]), "r"(a[1]), "r"(a[2]), "r"(a[3]), "r"(b[0]), "r"(b[1]));
}
__device__ __forceinline__ void cp16(void* sdst, const void* gsrc){
    unsigned sa = (unsigned)__cvta_generic_to_shared(sdst);
    asm volatile("cp.async.ca.shared.global [%0], [%1], 16;" :: "r"(sa), "l"(gsrc));
}
#define CP_COMMIT() asm volatile("cp.async.commit_group;")
#define CP_WAIT0()  asm volatile("cp.async.wait_group 0;")

// ---------------------------------------------------------------------------
// QKV GEMM (unchanged, known-good): scatter tf32 into g_q/g_k/g_v [bh][n][dh]
// ---------------------------------------------------------------------------
__global__ __launch_bounds__(256) void qkv_mma(const float* __restrict__ X,
                                               const float* __restrict__ W,
                                               const float* __restrict__ bias){
    __shared__ unsigned As[128*36];
    __shared__ unsigned Bs[32*132];
    const int tid = threadIdx.x, lane = tid & 31, warp = tid >> 5;
    const int wm = (warp >> 1) * 32, wn = (warp & 1) * 64;
    const int m0 = blockIdx.x * 128, n0 = blockIdx.y * 128;
    float c[2][8][4] = {};

    for (int k0 = 0; k0 < DMODEL; k0 += 32){
        #pragma unroll
        for (int l = 0; l < 4; l++){
            int idx = tid + l*256;
            int mm = idx >> 3, c4 = (idx & 7)*4;
            float4 v = *(const float4*)&X[(size_t)(m0+mm)*DMODEL + k0 + c4];
            unsigned* d = &As[mm*36 + c4];
            d[0]=f2t(v.x); d[1]=f2t(v.y); d[2]=f2t(v.z); d[3]=f2t(v.w);
        }
        #pragma unroll
        for (int l = 0; l < 4; l++){
            int idx = tid + l*256;
            int kk = idx >> 5, c4 = (idx & 31)*4;
            float4 v = *(const float4*)&W[(size_t)(k0+kk)*S3DIM + n0 + c4];
            unsigned* d = &Bs[kk*132 + c4];
            d[0]=f2t(v.x); d[1]=f2t(v.y); d[2]=f2t(v.z); d[3]=f2t(v.w);
        }
        __syncthreads();
        #pragma unroll
        for (int ks = 0; ks < 32; ks += 8){
            unsigned a[2][4];
            #pragma unroll
            for (int i = 0; i < 2; i++){
                int r = wm + i*16 + (lane>>2);
                a[i][0] = As[r*36     + ks + (lane&3)];
                a[i][1] = As[(r+8)*36 + ks + (lane&3)];
                a[i][2] = As[r*36     + ks + (lane&3) + 4];
                a[i][3] = As[(r+8)*36 + ks + (lane&3) + 4];
            }
            #pragma unroll
            for (int j = 0; j < 8; j++){
                unsigned b[2];
                b[0] = Bs[(ks + (lane&3))*132     + wn + j*8 + (lane>>2)];
                b[1] = Bs[(ks + (lane&3) + 4)*132 + wn + j*8 + (lane>>2)];
                mma_tf32(c[0][j], a[0], b);
                mma_tf32(c[1][j], a[1], b);
            }
        }
        __syncthreads();
    }
    #pragma unroll
    for (int j = 0; j < 8; j++){
        int n_abs = n0 + wn + j*8;
        int which = n_abs / DMODEL;
        int rem = n_abs - which*DMODEL;
        int h = rem >> 6;
        int dh0 = (rem & 63) + 2*(lane&3);
        unsigned* dst = (which==0) ? g_q : (which==1 ? g_k : g_v);
        float sc = (which==0) ? SCALE : 1.0f;
        float b0 = bias[n_abs + 2*(lane&3)], b1 = bias[n_abs + 2*(lane&3) + 1];
        #pragma unroll
        for (int i = 0; i < 2; i++){
            int gm = m0 + wm + i*16 + (lane>>2);
            #pragma unroll
            for (int half = 0; half < 2; half++){
                int r = gm + half*8;
                int bb = r >> 11, nn = r & (NSEQ-1);
                unsigned* row = dst + ((size_t)((bb*NH + h)*NSEQ + nn))*DH + dh0;
                row[0] = f2t((c[i][j][half*2+0] + b0) * sc);
                row[1] = f2t((c[i][j][half*2+1] + b1) * sc);
            }
        }
    }
}

// ---------------------------------------------------------------------------
// Repack row-major g_q/g_k/g_v into fragment order (bit-exact gather).
// grid: (6144, 3), 256 thr. y=0: Q (uint4), y=1: K (uint2), y=2: V (uint2).
// ---------------------------------------------------------------------------
__global__ __launch_bounds__(256) void repack(){
    int t = blockIdx.x*256 + threadIdx.x;
    int lane = t & 31, q = lane >> 2, k = lane & 3;
    if (blockIdx.y == 0){
        if (t >= NBH*128*8*32) return;
        int d8 = (t>>5)&7, qb = (t>>8)&127, bh = t>>15;
        const unsigned* src = g_q + ((size_t)(bh*NSEQ + qb*16))*DH + d8*8 + k;
        uint4 v;
        v.x = src[q*DH]; v.y = src[(q+8)*DH]; v.z = src[q*DH + 4]; v.w = src[(q+8)*DH + 4];
        g_qp[t] = v;
    } else if (blockIdx.y == 1){
        int d8 = (t>>5)&7, jb = (t>>8)&255, bh = t>>16;
        const unsigned* src = g_k + ((size_t)(bh*NSEQ + jb*8 + q))*DH + d8*8 + k;
        g_kp[t] = make_uint2(src[0], src[4]);
    } else {
        int j = (t>>5)&7, vb = (t>>8)&255, bh = t>>16;
        const unsigned* src = g_v + ((size_t)(bh*NSEQ + vb*8 + k))*DH + j*8 + q;
        g_vp[t] = make_uint2(src[0], src[4*DH]);
    }
}

// ---------------------------------------------------------------------------
// Flash attention v2: Q frags in regs, packed K/V via cp.async double buffer.
// CTA: one (b,h) x 128 Q rows, 8 warps (16 rows each), KV tiles of 64.
// smem: Kb[2][16K] Vb[2][16K] Ps[128][68] = 100352 B -> 2 CTAs/SM.
// ---------------------------------------------------------------------------
__global__ __launch_bounds__(256, 2) void attn_mma(){
    extern __shared__ unsigned sm[];
    uint2* Kb = (uint2*)sm;                 // [2][2048]
    uint2* Vb = Kb + 2*2048;                // [2][2048]
    unsigned* Ps = (unsigned*)(Vb + 2*2048);// [128*68]
    const int tid = threadIdx.x, lane = tid & 31, warp = tid >> 5;
    const int q0 = blockIdx.x * 128;
    const int bh = blockIdx.y;
    const int r0 = warp*16 + (lane>>2);

    // Q fragments (loop-invariant): coalesced LDG.128 x8
    uint4 aq[8];
    {
        const uint4* Qp = g_qp + ((size_t)(bh*128 + (q0>>4) + warp))*8*32 + lane;
        #pragma unroll
        for (int d8 = 0; d8 < 8; d8++) aq[d8] = Qp[d8*32];
    }
    const uint2* Kg = g_kp + (size_t)bh*256*8*32;   // tile t at + t*2048
    const uint2* Vg = g_vp + (size_t)bh*256*8*32;

    // prologue: tile 0
    #pragma unroll
    for (int i = 0; i < 4; i++){
        cp16(((uint4*)Kb) + tid + i*256, ((const uint4*)Kg) + tid + i*256);
        cp16(((uint4*)Vb) + tid + i*256, ((const uint4*)Vg) + tid + i*256);
    }
    CP_COMMIT();

    float o[8][4] = {};
    float mi0 = -1e30f, mi1 = -1e30f, li0 = 0.f, li1 = 0.f;

    for (int t = 0; t < NSEQ/64; t++){
        const uint2* Ks = Kb + (t&1)*2048;
        const uint2* Vs = Vb + (t&1)*2048;
        CP_WAIT0();
        __syncthreads();   // tile t visible; all warps done with buf[(t+1)&1]
        if (t < NSEQ/64 - 1){
            uint4* kd = (uint4*)(Kb + ((t+1)&1)*2048);
            uint4* vd = (uint4*)(Vb + ((t+1)&1)*2048);
            const uint4* ks = (const uint4*)(Kg + (t+1)*2048);
            const uint4* vs = (const uint4*)(Vg + (t+1)*2048);
            #pragma unroll
            for (int i = 0; i < 4; i++){
                cp16(kd + tid + i*256, ks + tid + i*256);
                cp16(vd + tid + i*256, vs + tid + i*256);
            }
            CP_COMMIT();
        }

        // S = Q @ K^T  (Q pre-scaled by SCALE)
        float s[8][4] = {};
        #pragma unroll
        for (int d8 = 0; d8 < 8; d8++){
            unsigned a[4] = {aq[d8].x, aq[d8].y, aq[d8].z, aq[d8].w};
            #pragma unroll
            for (int j = 0; j < 8; j++){
                uint2 bv = Ks[(j*8 + d8)*32 + lane];
                unsigned b[2] = {bv.x, bv.y};
                mma_tf32(s[j], a, b);
            }
        }

        // online softmax: rows r0 (c0,c1) and r0+8 (c2,c3)
        float rm0 = -1e30f, rm1 = -1e30f;
        #pragma unroll
        for (int j = 0; j < 8; j++){
            rm0 = fmaxf(rm0, fmaxf(s[j][0], s[j][1]));
            rm1 = fmaxf(rm1, fmaxf(s[j][2], s[j][3]));
        }
        rm0 = fmaxf(rm0, __shfl_xor_sync(0xffffffffu, rm0, 1));
        rm0 = fmaxf(rm0, __shfl_xor_sync(0xffffffffu, rm0, 2));
        rm1 = fmaxf(rm1, __shfl_xor_sync(0xffffffffu, rm1, 1));
        rm1 = fmaxf(rm1, __shfl_xor_sync(0xffffffffu, rm1, 2));
        float mn0 = fmaxf(mi0, rm0), mn1 = fmaxf(mi1, rm1);
        float f0 = __expf(mi0 - mn0), f1 = __expf(mi1 - mn1);
        float sum0 = 0.f, sum1 = 0.f;
        #pragma unroll
        for (int j = 0; j < 8; j++){
            s[j][0] = __expf(s[j][0]-mn0); s[j][1] = __expf(s[j][1]-mn0);
            s[j][2] = __expf(s[j][2]-mn1); s[j][3] = __expf(s[j][3]-mn1);
            sum0 += s[j][0]+s[j][1];       sum1 += s[j][2]+s[j][3];
            o[j][0]*=f0; o[j][1]*=f0; o[j][2]*=f1; o[j][3]*=f1;
        }
        sum0 += __shfl_xor_sync(0xffffffffu, sum0, 1);
        sum0 += __shfl_xor_sync(0xffffffffu, sum0, 2);
        sum1 += __shfl_xor_sync(0xffffffffu, sum1, 1);
        sum1 += __shfl_xor_sync(0xffffffffu, sum1, 2);
        li0 = li0*f0 + sum0; li1 = li1*f1 + sum1;
        mi0 = mn0; mi1 = mn1;

        // P -> smem (own rows only), STS.64
        #pragma unroll
        for (int j = 0; j < 8; j++){
            int cc = j*8 + 2*(lane&3);
            *(uint2*)&Ps[r0*68 + cc]     = make_uint2(f2t(s[j][0]), f2t(s[j][1]));
            *(uint2*)&Ps[(r0+8)*68 + cc] = make_uint2(f2t(s[j][2]), f2t(s[j][3]));
        }
        __syncwarp();

        // O += P @ V
        #pragma unroll
        for (int kb = 0; kb < 8; kb++){
            int kn = kb*8;
            unsigned a[4];
            a[0] = Ps[r0*68     + kn + (lane&3)];
            a[1] = Ps[(r0+8)*68 + kn + (lane&3)];
            a[2] = Ps[r0*68     + kn + (lane&3) + 4];
            a[3] = Ps[(r0+8)*68 + kn + (lane&3) + 4];
            #pragma unroll
            for (int j = 0; j < 8; j++){
                uint2 bv = Vs[(kb*8 + j)*32 + lane];
                unsigned b[2] = {bv.x, bv.y};
                mma_tf32(o[j], a, b);
            }
        }
    }

    // epilogue -> g_att[b*N+n][h*64+dh] as tf32 bits
    const int b = bh / NH, h = bh % NH;
    float inv0 = 1.f/li0, inv1 = 1.f/li1;
    #pragma unroll
    for (int j = 0; j < 8; j++){
        int dh = j*8 + 2*(lane&3);
        int row0 = q0 + r0, row1 = row0 + 8;
        unsigned* p0 = g_att + ((size_t)(b*NSEQ + row0))*DMODEL + h*DH + dh;
        unsigned* p1 = g_att + ((size_t)(b*NSEQ + row1))*DMODEL + h*DH + dh;
        p0[0] = f2t(o[j][0]*inv0); p0[1] = f2t(o[j][1]*inv0);
        p1[0] = f2t(o[j][2]*inv1); p1[1] = f2t(o[j][3]*inv1);
    }
}

// ---------------------------------------------------------------------------
// Output projection (unchanged): out = g_att @ Wproj + b
// ---------------------------------------------------------------------------
__global__ __launch_bounds__(256) void proj_mma(const float* __restrict__ W,
                                                const float* __restrict__ bias,
                                                float* __restrict__ out){
    __shared__ unsigned As[128*36];
    __shared__ unsigned Bs[32*132];
    const int tid = threadIdx.x, lane = tid & 31, warp = tid >> 5;
    const int wm = (warp >> 1) * 32, wn = (warp & 1) * 64;
    const int m0 = blockIdx.x * 128, n0 = blockIdx.y * 128;
    float c[2][8][4] = {};

    for (int k0 = 0; k0 < DMODEL; k0 += 32){
        #pragma unroll
        for (int l = 0; l < 4; l++){
            int idx = tid + l*256;
            int mm = idx >> 3, c4 = (idx & 7)*4;
            uint4 v = *(const uint4*)&g_att[(size_t)(m0+mm)*DMODEL + k0 + c4];
            unsigned* d = &As[mm*36 + c4];
            d[0]=v.x; d[1]=v.y; d[2]=v.z; d[3]=v.w;
        }
        #pragma unroll
        for (int l = 0; l < 4; l++){
            int idx = tid + l*256;
            int kk = idx >> 5, c4 = (idx & 31)*4;
            float4 v = *(const float4*)&W[(size_t)(k0+kk)*DMODEL + n0 + c4];
            unsigned* d = &Bs[kk*132 + c4];
            d[0]=f2t(v.x); d[1]=f2t(v.y); d[2]=f2t(v.z); d[3]=f2t(v.w);
        }
        __syncthreads();
        #pragma unroll
        for (int ks = 0; ks < 32; ks += 8){
            unsigned a[2][4];
            #pragma unroll
            for (int i = 0; i < 2; i++){
                int r = wm + i*16 + (lane>>2);
                a[i][0] = As[r*36     + ks + (lane&3)];
                a[i][1] = As[(r+8)*36 + ks + (lane&3)];
                a[i][2] = As[r*36     + ks + (lane&3) + 4];
                a[i][3] = As[(r+8)*36 + ks + (lane&3) + 4];
            }
            #pragma unroll
            for (int j = 0; j < 8; j++){
                unsigned b[2];
                b[0] = Bs[(ks + (lane&3))*132     + wn + j*8 + (lane>>2)];
                b[1] = Bs[(ks + (lane&3) + 4)*132 + wn + j*8 + (lane>>2)];
                mma_tf32(c[0][j], a[0], b);
                mma_tf32(c[1][j], a[1], b);
            }
        }
        __syncthreads();
    }
    #pragma unroll
    for (int j = 0; j < 8; j++){
        int gn = n0 + wn + j*8 + 2*(lane&3);
        float b0 = bias[gn], b1 = bias[gn+1];
        #pragma unroll
        for (int i = 0; i < 2; i++){
            int gm = m0 + wm + i*16 + (lane>>2);
            #pragma unroll
            for (int half = 0; half < 2; half++){
                float* p = &out[(size_t)(gm + half*8)*DMODEL + gn];
                p[0] = c[i][j][half*2+0] + b0;
                p[1] = c[i][j][half*2+1] + b1;
            }
        }
    }
}

// ---------------------------------------------------------------------------
extern "C" void kernel_launch(void* const* d_in, const int* in_sizes, int n_in,
                              void* d_out, int out_size) {
    const float* x      = (const float*)d_in[0];
    const float* w_qkv  = (const float*)d_in[1];
    const float* b_qkv  = (const float*)d_in[2];
    const float* w_proj = (const float*)d_in[3];
    const float* b_proj = (const float*)d_in[4];
    float* out = (float*)d_out;

    const int attn_smem = (2*2048 + 2*2048)*8 + 128*68*4;   // 100352
    cudaFuncSetAttribute(attn_mma, cudaFuncAttributeMaxDynamicSharedMemorySize, attn_smem);

    qkv_mma <<<dim3(32, 18), 256>>>(x, w_qkv, b_qkv);
    repack  <<<dim3(6144, 3), 256>>>();
    attn_mma<<<dim3(16, 24), 256, attn_smem>>>();
    proj_mma<<<dim3(32, 6),  256>>>(w_proj, b_proj, out);
}

// round 8
// speedup vs baseline: 1.2844x; 1.2844x over previous
#include <cuda_runtime.h>

#define NSEQ  2048
#define DMODEL 768
#define NH    12
#define DH    64
#define BATCH 2
#define MROWS 4096          // BATCH*NSEQ
#define S3DIM 2304          // 3*DMODEL
#define SCALE 0.125f        // DH^-0.5
#define NBH   (BATCH*NH)    // 24

// Scratch (tf32 bit patterns stored as unsigned)
__device__ unsigned g_q[BATCH*NH*NSEQ*DH];   // [bh][n][dh]
__device__ unsigned g_k[BATCH*NH*NSEQ*DH];
__device__ unsigned g_v[BATCH*NH*NSEQ*DH];
__device__ unsigned g_att[MROWS*DMODEL];

__device__ __forceinline__ unsigned f2t(float f){
    unsigned u; asm("cvt.rna.tf32.f32 %0, %1;" : "=r"(u) : "f"(f)); return u;
}
__device__ __forceinline__ void mma_tf32(float c[4], const unsigned a[4], const unsigned b[2]){
    asm volatile("mma.sync.aligned.m16n8k8.row.col.f32.tf32.tf32.f32 "
        "{%0,%1,%2,%3}, {%4,%5,%6,%7}, {%8,%9}, {%0,%1,%2,%3};"
        : "+f"(c[0]), "+f"(c[1]), "+f"(c[2]), "+f"(c[3])
        : "r"(a[0]), "r"(a[1]), "r"(a[2]), "r"(a[3]), "r"(b[0]), "r"(b[1]));
}
__device__ __forceinline__ void cp16(void* sdst, const void* gsrc){
    unsigned sa = (unsigned)__cvta_generic_to_shared(sdst);
    asm volatile("cp.async.ca.shared.global [%0], [%1], 16;" :: "r"(sa), "l"(gsrc));
}
#define CP_COMMIT() asm volatile("cp.async.commit_group;")
#define CP_WAIT0()  asm volatile("cp.async.wait_group 0;")

#define A_STRIDE 36
#define B_STRIDE 132
#define A_TILE (128*A_STRIDE)   // floats per A buffer
#define B_TILE (32*B_STRIDE)    // floats per B buffer
#define GEMM_SMEM ((2*A_TILE + 2*B_TILE)*4)   // 70656 B

// ---------------------------------------------------------------------------
// QKV GEMM: [4096,768]@[768,2304] -> g_q/g_k/g_v [bh][n][dh] (tf32 bits).
// cp.async double-buffered k-chunks; cvt.rna at fragment read.
// ---------------------------------------------------------------------------
__global__ __launch_bounds__(256) void qkv_mma(const float* __restrict__ X,
                                               const float* __restrict__ W,
                                               const float* __restrict__ bias){
    extern __shared__ float smf[];
    float* Asf = smf;               // [2][128*36]
    float* Bsf = smf + 2*A_TILE;    // [2][32*132]
    const int tid = threadIdx.x, lane = tid & 31, warp = tid >> 5;
    const int wm = (warp >> 1) * 32, wn = (warp & 1) * 64;
    const int m0 = blockIdx.x * 128, n0 = blockIdx.y * 128;
    float c[2][8][4] = {};

    // per-thread load coords
    const int amm = tid >> 3,  ac4 = (tid & 7) * 4;     // + l*32 rows
    const int bkk = tid >> 5,  bc4 = (tid & 31) * 4;    // + l*8 rows

    #define LOAD_CHUNK_Q(k0, buf) do{                                        \
        float* Ad = Asf + (buf)*A_TILE;                                      \
        float* Bd = Bsf + (buf)*B_TILE;                                      \
        _Pragma("unroll")                                                    \
        for (int l = 0; l < 4; l++)                                          \
            cp16(&Ad[(amm + l*32)*A_STRIDE + ac4],                           \
                 &X[(size_t)(m0 + amm + l*32)*DMODEL + (k0) + ac4]);         \
        _Pragma("unroll")                                                    \
        for (int l = 0; l < 4; l++)                                          \
            cp16(&Bd[(bkk + l*8)*B_STRIDE + bc4],                            \
                 &W[(size_t)((k0) + bkk + l*8)*S3DIM + n0 + bc4]);           \
    }while(0)

    LOAD_CHUNK_Q(0, 0);
    CP_COMMIT();

    for (int ch = 0; ch < DMODEL/32; ch++){
        CP_WAIT0();
        __syncthreads();
        if (ch + 1 < DMODEL/32){
            LOAD_CHUNK_Q((ch+1)*32, (ch+1)&1);
            CP_COMMIT();
        }
        const float* As = Asf + (ch&1)*A_TILE;
        const float* Bs = Bsf + (ch&1)*B_TILE;
        #pragma unroll
        for (int ks = 0; ks < 32; ks += 8){
            unsigned a[2][4];
            #pragma unroll
            for (int i = 0; i < 2; i++){
                int r = wm + i*16 + (lane>>2);
                a[i][0] = f2t(As[r*A_STRIDE     + ks + (lane&3)]);
                a[i][1] = f2t(As[(r+8)*A_STRIDE + ks + (lane&3)]);
                a[i][2] = f2t(As[r*A_STRIDE     + ks + (lane&3) + 4]);
                a[i][3] = f2t(As[(r+8)*A_STRIDE + ks + (lane&3) + 4]);
            }
            #pragma unroll
            for (int j = 0; j < 8; j++){
                unsigned b[2];
                b[0] = f2t(Bs[(ks + (lane&3))*B_STRIDE     + wn + j*8 + (lane>>2)]);
                b[1] = f2t(Bs[(ks + (lane&3) + 4)*B_STRIDE + wn + j*8 + (lane>>2)]);
                mma_tf32(c[0][j], a[0], b);
                mma_tf32(c[1][j], a[1], b);
            }
        }
    }

    // epilogue: scatter, q pre-scaled by SCALE (exact pow2)
    #pragma unroll
    for (int j = 0; j < 8; j++){
        int n_abs = n0 + wn + j*8;
        int which = n_abs / DMODEL;
        int rem = n_abs - which*DMODEL;
        int h = rem >> 6;
        int dh0 = (rem & 63) + 2*(lane&3);
        unsigned* dst = (which==0) ? g_q : (which==1 ? g_k : g_v);
        float sc = (which==0) ? SCALE : 1.0f;
        float b0 = bias[n_abs + 2*(lane&3)], b1 = bias[n_abs + 2*(lane&3) + 1];
        #pragma unroll
        for (int i = 0; i < 2; i++){
            int gm = m0 + wm + i*16 + (lane>>2);
            #pragma unroll
            for (int half = 0; half < 2; half++){
                int r = gm + half*8;
                int bb = r >> 11, nn = r & (NSEQ-1);
                unsigned* row = dst + ((size_t)((bb*NH + h)*NSEQ + nn))*DH + dh0;
                row[0] = f2t((c[i][j][half*2+0] + b0) * sc);
                row[1] = f2t((c[i][j][half*2+1] + b1) * sc);
            }
        }
    }
}

// ---------------------------------------------------------------------------
// Flash attention (R4 known-good). CTA: one (b,h), 128 Q rows, 8 warps.
// smem: Qs[128][68] Ks[64][68] Vs[64][68] Ps[128][68] = 104448 B.
// ---------------------------------------------------------------------------
__global__ __launch_bounds__(256) void attn_mma(){
    extern __shared__ unsigned sm[];
    unsigned* Qs = sm;               // [128][68]
    unsigned* Ks = Qs + 128*68;      // [64][68]
    unsigned* Vs = Ks + 64*68;       // [64][68]
    unsigned* Ps = Vs + 64*68;       // [128][68]
    const int tid = threadIdx.x, lane = tid & 31, warp = tid >> 5;
    const int q0 = blockIdx.x * 128;
    const int bh = blockIdx.y;
    const unsigned* Qg = g_q + (size_t)bh*NSEQ*DH;
    const unsigned* Kg = g_k + (size_t)bh*NSEQ*DH;
    const unsigned* Vg = g_v + (size_t)bh*NSEQ*DH;

    #pragma unroll
    for (int l = 0; l < 8; l++){
        int idx = tid + l*256;
        int mm = idx >> 4, c4 = (idx & 15)*4;
        uint4 v = *(const uint4*)&Qg[(size_t)(q0+mm)*DH + c4];
        unsigned* d = &Qs[mm*68 + c4];
        d[0]=v.x; d[1]=v.y; d[2]=v.z; d[3]=v.w;
    }

    float o[8][4] = {};
    float mi0 = -1e30f, mi1 = -1e30f, li0 = 0.f, li1 = 0.f;
    const int r0 = warp*16 + (lane>>2);

    for (int t = 0; t < NSEQ/64; t++){
        __syncthreads();
        #pragma unroll
        for (int l = 0; l < 4; l++){
            int idx = tid + l*256;
            int nn = idx >> 4, c4 = (idx & 15)*4;
            uint4 kv = *(const uint4*)&Kg[(size_t)(t*64+nn)*DH + c4];
            unsigned* d = &Ks[nn*68 + c4];
            d[0]=kv.x; d[1]=kv.y; d[2]=kv.z; d[3]=kv.w;
            uint4 vv = *(const uint4*)&Vg[(size_t)(t*64+nn)*DH + c4];
            unsigned* e = &Vs[nn*68 + c4];
            e[0]=vv.x; e[1]=vv.y; e[2]=vv.z; e[3]=vv.w;
        }
        __syncthreads();

        // S = Q @ K^T  (Q pre-scaled)
        float s[8][4] = {};
        #pragma unroll
        for (int d8 = 0; d8 < 64; d8 += 8){
            unsigned a[4];
            a[0] = Qs[r0*68     + d8 + (lane&3)];
            a[1] = Qs[(r0+8)*68 + d8 + (lane&3)];
            a[2] = Qs[r0*68     + d8 + (lane&3) + 4];
            a[3] = Qs[(r0+8)*68 + d8 + (lane&3) + 4];
            #pragma unroll
            for (int j = 0; j < 8; j++){
                unsigned b[2];
                b[0] = Ks[(j*8 + (lane>>2))*68 + d8 + (lane&3)];
                b[1] = Ks[(j*8 + (lane>>2))*68 + d8 + (lane&3) + 4];
                mma_tf32(s[j], a, b);
            }
        }

        // online softmax
        float rm0 = -1e30f, rm1 = -1e30f;
        #pragma unroll
        for (int j = 0; j < 8; j++){
            rm0 = fmaxf(rm0, fmaxf(s[j][0], s[j][1]));
            rm1 = fmaxf(rm1, fmaxf(s[j][2], s[j][3]));
        }
        rm0 = fmaxf(rm0, __shfl_xor_sync(0xffffffffu, rm0, 1));
        rm0 = fmaxf(rm0, __shfl_xor_sync(0xffffffffu, rm0, 2));
        rm1 = fmaxf(rm1, __shfl_xor_sync(0xffffffffu, rm1, 1));
        rm1 = fmaxf(rm1, __shfl_xor_sync(0xffffffffu, rm1, 2));
        float mn0 = fmaxf(mi0, rm0), mn1 = fmaxf(mi1, rm1);
        float f0 = __expf(mi0 - mn0), f1 = __expf(mi1 - mn1);
        float sum0 = 0.f, sum1 = 0.f;
        #pragma unroll
        for (int j = 0; j < 8; j++){
            s[j][0] = __expf(s[j][0]-mn0); s[j][1] = __expf(s[j][1]-mn0);
            s[j][2] = __expf(s[j][2]-mn1); s[j][3] = __expf(s[j][3]-mn1);
            sum0 += s[j][0]+s[j][1];       sum1 += s[j][2]+s[j][3];
            o[j][0]*=f0; o[j][1]*=f0; o[j][2]*=f1; o[j][3]*=f1;
        }
        sum0 += __shfl_xor_sync(0xffffffffu, sum0, 1);
        sum0 += __shfl_xor_sync(0xffffffffu, sum0, 2);
        sum1 += __shfl_xor_sync(0xffffffffu, sum1, 1);
        sum1 += __shfl_xor_sync(0xffffffffu, sum1, 2);
        li0 = li0*f0 + sum0; li1 = li1*f1 + sum1;
        mi0 = mn0; mi1 = mn1;

        // P -> smem (own rows only)
        #pragma unroll
        for (int j = 0; j < 8; j++){
            int cc = j*8 + 2*(lane&3);
            *(uint2*)&Ps[r0*68 + cc]     = make_uint2(f2t(s[j][0]), f2t(s[j][1]));
            *(uint2*)&Ps[(r0+8)*68 + cc] = make_uint2(f2t(s[j][2]), f2t(s[j][3]));
        }
        __syncwarp();

        // O += P @ V
        #pragma unroll
        for (int kn = 0; kn < 64; kn += 8){
            unsigned a[4];
            a[0] = Ps[r0*68     + kn + (lane&3)];
            a[1] = Ps[(r0+8)*68 + kn + (lane&3)];
            a[2] = Ps[r0*68     + kn + (lane&3) + 4];
            a[3] = Ps[(r0+8)*68 + kn + (lane&3) + 4];
            #pragma unroll
            for (int j = 0; j < 8; j++){
                unsigned b[2];
                b[0] = Vs[(kn + (lane&3))*68     + j*8 + (lane>>2)];
                b[1] = Vs[(kn + (lane&3) + 4)*68 + j*8 + (lane>>2)];
                mma_tf32(o[j], a, b);
            }
        }
    }

    // epilogue -> g_att[b*N+n][h*64+dh]
    const int b = bh / NH, h = bh % NH;
    float inv0 = 1.f/li0, inv1 = 1.f/li1;
    #pragma unroll
    for (int j = 0; j < 8; j++){
        int dh = j*8 + 2*(lane&3);
        int row0 = q0 + r0, row1 = row0 + 8;
        unsigned* p0 = g_att + ((size_t)(b*NSEQ + row0))*DMODEL + h*DH + dh;
        unsigned* p1 = g_att + ((size_t)(b*NSEQ + row1))*DMODEL + h*DH + dh;
        p0[0] = f2t(o[j][0]*inv0); p0[1] = f2t(o[j][1]*inv0);
        p1[0] = f2t(o[j][2]*inv1); p1[1] = f2t(o[j][3]*inv1);
    }
}

// ---------------------------------------------------------------------------
// Projection: out = g_att @ Wproj + b. Same cp.async pipeline; A comes from
// g_att (already tf32 bits — reinterpret as float for cp.async, cvt is no-op
// safe since values are exact tf32).
// ---------------------------------------------------------------------------
__global__ __launch_bounds__(256) void proj_mma(const float* __restrict__ W,
                                                const float* __restrict__ bias,
                                                float* __restrict__ out){
    extern __shared__ float smf[];
    float* Asf = smf;
    float* Bsf = smf + 2*A_TILE;
    const int tid = threadIdx.x, lane = tid & 31, warp = tid >> 5;
    const int wm = (warp >> 1) * 32, wn = (warp & 1) * 64;
    const int m0 = blockIdx.x * 128, n0 = blockIdx.y * 128;
    float c[2][8][4] = {};
    const float* Ag = (const float*)g_att;

    const int amm = tid >> 3,  ac4 = (tid & 7) * 4;
    const int bkk = tid >> 5,  bc4 = (tid & 31) * 4;

    #define LOAD_CHUNK_P(k0, buf) do{                                        \
        float* Ad = Asf + (buf)*A_TILE;                                      \
        float* Bd = Bsf + (buf)*B_TILE;                                      \
        _Pragma("unroll")                                                    \
        for (int l = 0; l < 4; l++)                                          \
            cp16(&Ad[(amm + l*32)*A_STRIDE + ac4],                           \
                 &Ag[(size_t)(m0 + amm + l*32)*DMODEL + (k0) + ac4]);        \
        _Pragma("unroll")                                                    \
        for (int l = 0; l < 4; l++)                                          \
            cp16(&Bd[(bkk + l*8)*B_STRIDE + bc4],                            \
                 &W[(size_t)((k0) + bkk + l*8)*DMODEL + n0 + bc4]);          \
    }while(0)

    LOAD_CHUNK_P(0, 0);
    CP_COMMIT();

    for (int ch = 0; ch < DMODEL/32; ch++){
        CP_WAIT0();
        __syncthreads();
        if (ch + 1 < DMODEL/32){
            LOAD_CHUNK_P((ch+1)*32, (ch+1)&1);
            CP_COMMIT();
        }
        const float* As = Asf + (ch&1)*A_TILE;
        const float* Bs = Bsf + (ch&1)*B_TILE;
        #pragma unroll
        for (int ks = 0; ks < 32; ks += 8){
            unsigned a[2][4];
            #pragma unroll
            for (int i = 0; i < 2; i++){
                int r = wm + i*16 + (lane>>2);
                a[i][0] = __float_as_uint(As[r*A_STRIDE     + ks + (lane&3)]);
                a[i][1] = __float_as_uint(As[(r+8)*A_STRIDE + ks + (lane&3)]);
                a[i][2] = __float_as_uint(As[r*A_STRIDE     + ks + (lane&3) + 4]);
                a[i][3] = __float_as_uint(As[(r+8)*A_STRIDE + ks + (lane&3) + 4]);
            }
            #pragma unroll
            for (int j = 0; j < 8; j++){
                unsigned b[2];
                b[0] = f2t(Bs[(ks + (lane&3))*B_STRIDE     + wn + j*8 + (lane>>2)]);
                b[1] = f2t(Bs[(ks + (lane&3) + 4)*B_STRIDE + wn + j*8 + (lane>>2)]);
                mma_tf32(c[0][j], a[0], b);
                mma_tf32(c[1][j], a[1], b);
            }
        }
    }

    #pragma unroll
    for (int j = 0; j < 8; j++){
        int gn = n0 + wn + j*8 + 2*(lane&3);
        float b0 = bias[gn], b1 = bias[gn+1];
        #pragma unroll
        for (int i = 0; i < 2; i++){
            int gm = m0 + wm + i*16 + (lane>>2);
            #pragma unroll
            for (int half = 0; half < 2; half++){
                float* p = &out[(size_t)(gm + half*8)*DMODEL + gn];
                p[0] = c[i][j][half*2+0] + b0;
                p[1] = c[i][j][half*2+1] + b1;
            }
        }
    }
}

// ---------------------------------------------------------------------------
extern "C" void kernel_launch(void* const* d_in, const int* in_sizes, int n_in,
                              void* d_out, int out_size) {
    const float* x      = (const float*)d_in[0];
    const float* w_qkv  = (const float*)d_in[1];
    const float* b_qkv  = (const float*)d_in[2];
    const float* w_proj = (const float*)d_in[3];
    const float* b_proj = (const float*)d_in[4];
    float* out = (float*)d_out;

    const int attn_smem = (128*68 + 64*68 + 64*68 + 128*68) * 4;  // 104448
    cudaFuncSetAttribute(attn_mma, cudaFuncAttributeMaxDynamicSharedMemorySize, attn_smem);
    cudaFuncSetAttribute(qkv_mma,  cudaFuncAttributeMaxDynamicSharedMemorySize, GEMM_SMEM);
    cudaFuncSetAttribute(proj_mma, cudaFuncAttributeMaxDynamicSharedMemorySize, GEMM_SMEM);

    qkv_mma <<<dim3(32, 18), 256, GEMM_SMEM>>>(x, w_qkv, b_qkv);
    attn_mma<<<dim3(16, 24), 256, attn_smem>>>();
    proj_mma<<<dim3(32, 6),  256, GEMM_SMEM>>>(w_proj, b_proj, out);
}

// round 10
// speedup vs baseline: 1.5637x; 1.2175x over previous
#include <cuda_runtime.h>

#define NSEQ  2048
#define DMODEL 768
#define NH    12
#define DH    64
#define BATCH 2
#define MROWS 4096          // BATCH*NSEQ
#define S3DIM 2304          // 3*DMODEL
#define SCALE 0.125f
#define NBH   (BATCH*NH)    // 24
#define K8S   (DMODEL/8)    // 96 k8-steps

// Row-major scratch (tf32 bits)
__device__ unsigned g_q[BATCH*NH*NSEQ*DH];
__device__ unsigned g_k[BATCH*NH*NSEQ*DH];
__device__ unsigned g_v[BATCH*NH*NSEQ*DH];
__device__ unsigned g_att[MROWS*DMODEL];

// Fragment-packed operands
__device__ uint4 g_xp [256*K8S*32];     // X:    [mb(16-row)][k8][lane] A-frag
__device__ uint2 g_wqp[288*K8S*32];     // Wqkv: [nb(8-col)][k8][lane]  B-frag
__device__ uint2 g_wpp[ 96*K8S*32];     // Wproj B-frag
__device__ uint4 g_ap [256*K8S*32];     // attn out A-frag (for proj)
__device__ uint4 g_qp [NBH*128*8*32];   // Q A-frag  [bh][qb][d8][lane]
__device__ uint2 g_kp [NBH*256*8*32];   // K B-frag  [bh][jb][d8][lane]
__device__ uint2 g_vp [NBH*256*8*32];   // V B-frag  [bh][vb][j][lane]

__device__ __forceinline__ unsigned f2t(float f){
    unsigned u; asm("cvt.rna.tf32.f32 %0, %1;" : "=r"(u) : "f"(f)); return u;
}
__device__ __forceinline__ void mma_tf32(float c[4], const unsigned a[4], const unsigned b[2]){
    asm volatile("mma.sync.aligned.m16n8k8.row.col.f32.tf32.tf32.f32 "
        "{%0,%1,%2,%3}, {%4,%5,%6,%7}, {%8,%9}, {%0,%1,%2,%3};"
        : "+f"(c[0]), "+f"(c[1]), "+f"(c[2]), "+f"(c[3])
        : "r"(a[0]), "r"(a[1]), "r"(a[2]), "r"(a[3]), "r"(b[0]), "r"(b[1]));
}
__device__ __forceinline__ void cp16(void* sdst, const void* gsrc){
    unsigned sa = (unsigned)__cvta_generic_to_shared(sdst);
    asm volatile("cp.async.ca.shared.global [%0], [%1], 16;" :: "r"(sa), "l"(gsrc));
}
#define CP_COMMIT() asm volatile("cp.async.commit_group;")
#define CP_WAIT0()  asm volatile("cp.async.wait_group 0;")

// ---------------------------------------------------------------------------
// Pack kernels (bit-exact gathers; tf32 conversion happens once, here)
// ---------------------------------------------------------------------------
__global__ __launch_bounds__(256) void x_pack(const float* __restrict__ X){
    int t = blockIdx.x*256 + threadIdx.x;          // 256*96*32
    int lane = t & 31, q = lane >> 2, k = lane & 3;
    int k8 = (t >> 5) % K8S, mb = (t >> 5) / K8S;
    int r = mb*16 + q, c = k8*8 + k;
    uint4 v;
    v.x = f2t(X[(size_t)r*DMODEL + c]);
    v.y = f2t(X[(size_t)(r+8)*DMODEL + c]);
    v.z = f2t(X[(size_t)r*DMODEL + c + 4]);
    v.w = f2t(X[(size_t)(r+8)*DMODEL + c + 4]);
    g_xp[t] = v;
}
__global__ __launch_bounds__(256) void wq_pack(const float* __restrict__ W){
    int t = blockIdx.x*256 + threadIdx.x;          // 288*96*32
    int lane = t & 31;
    int k8 = (t >> 5) % K8S, nb = (t >> 5) / K8S;
    int r = k8*8 + (lane & 3), c = nb*8 + (lane >> 2);
    g_wqp[t] = make_uint2(f2t(W[(size_t)r*S3DIM + c]), f2t(W[(size_t)(r+4)*S3DIM + c]));
}
__global__ __launch_bounds__(256) void wp_pack(const float* __restrict__ W){
    int t = blockIdx.x*256 + threadIdx.x;          // 96*96*32
    int lane = t & 31;
    int k8 = (t >> 5) % K8S, nb = (t >> 5) / K8S;
    int r = k8*8 + (lane & 3), c = nb*8 + (lane >> 2);
    g_wpp[t] = make_uint2(f2t(W[(size_t)r*DMODEL + c]), f2t(W[(size_t)(r+4)*DMODEL + c]));
}
__global__ __launch_bounds__(256) void att_pack(){
    int t = blockIdx.x*256 + threadIdx.x;          // 256*96*32
    int lane = t & 31, q = lane >> 2, k = lane & 3;
    int k8 = (t >> 5) % K8S, mb = (t >> 5) / K8S;
    int r = mb*16 + q, c = k8*8 + k;
    uint4 v;
    v.x = g_att[(size_t)r*DMODEL + c];
    v.y = g_att[(size_t)(r+8)*DMODEL + c];
    v.z = g_att[(size_t)r*DMODEL + c + 4];
    v.w = g_att[(size_t)(r+8)*DMODEL + c + 4];
    g_ap[t] = v;
}
// Q/K/V repack (proven bit-exact in R6)
__global__ __launch_bounds__(256) void repack(){
    int t = blockIdx.x*256 + threadIdx.x;
    int lane = t & 31, q = lane >> 2, k = lane & 3;
    if (blockIdx.y == 0){
        if (t >= NBH*128*8*32) return;
        int d8 = (t>>5)&7, qb = (t>>8)&127, bh = t>>15;
        const unsigned* src = g_q + ((size_t)(bh*NSEQ + qb*16))*DH + d8*8 + k;
        uint4 v;
        v.x = src[q*DH]; v.y = src[(q+8)*DH]; v.z = src[q*DH + 4]; v.w = src[(q+8)*DH + 4];
        g_qp[t] = v;
    } else if (blockIdx.y == 1){
        int d8 = (t>>5)&7, jb = (t>>8)&255, bh = t>>16;
        const unsigned* src = g_k + ((size_t)(bh*NSEQ + jb*8 + q))*DH + d8*8 + k;
        g_kp[t] = make_uint2(src[0], src[4]);
    } else {
        int j = (t>>5)&7, vb = (t>>8)&255, bh = t>>16;
        const unsigned* src = g_v + ((size_t)(bh*NSEQ + vb*8 + k))*DH + j*8 + q;
        g_vp[t] = make_uint2(src[0], src[4*DH]);
    }
}

// ---------------------------------------------------------------------------
// Packed-operand GEMM core. smem: A 2x16KB (uint4) + B 2x16KB (uint2) = 64KB.
// Chunk = 4 k8-steps (k=32). CTA 128x128, 8 warps (4m x 2n).
// ---------------------------------------------------------------------------
#define GEMM_SMEM2 65536

__device__ __forceinline__ void gemm_load_chunk(uint4* Abuf, uint4* Bbuf4,
                                                const uint4* Aglob, const uint2* Bglob,
                                                int mb0, int nb0, int ch4, int tid){
    #pragma unroll
    for (int l = 0; l < 4; l++){
        int i = tid + l*256;                       // A: 1024 uint4
        int mbL = i >> 7, k8l = (i >> 5) & 3, ln = i & 31;
        cp16(Abuf + i, Aglob + ((size_t)(mb0+mbL)*K8S + ch4 + k8l)*32 + ln);
    }
    #pragma unroll
    for (int l = 0; l < 4; l++){
        int i = tid + l*256;                       // B: 1024 uint4 (2048 uint2)
        int nbL = i >> 6, k8l = (i >> 4) & 3, u4 = i & 15;
        cp16(Bbuf4 + i, (const uint4*)(Bglob + ((size_t)(nb0+nbL)*K8S + ch4 + k8l)*32) + u4);
    }
}

__device__ __forceinline__ void gemm_main(float c[2][8][4], uint4* Asp, uint4* Bsp4,
                                          const uint4* Aglob, const uint2* Bglob,
                                          int mb0, int nb0, int tid, int lane, int warp){
    const int wmb = (warp >> 1)*2, wnb = (warp & 1)*8;
    gemm_load_chunk(Asp, Bsp4, Aglob, Bglob, mb0, nb0, 0, tid);
    CP_COMMIT();
    for (int ch = 0; ch < 24; ch++){
        CP_WAIT0();
        __syncthreads();
        if (ch + 1 < 24){
            gemm_load_chunk(Asp + ((ch+1)&1)*1024, Bsp4 + ((ch+1)&1)*1024,
                            Aglob, Bglob, mb0, nb0, (ch+1)*4, tid);
            CP_COMMIT();
        }
        const uint4* As = Asp + (ch&1)*1024;
        const uint2* Bs = (const uint2*)(Bsp4 + (ch&1)*1024);
        #pragma unroll
        for (int k8l = 0; k8l < 4; k8l++){
            uint4 A0 = As[((wmb+0)*4 + k8l)*32 + lane];
            uint4 A1 = As[((wmb+1)*4 + k8l)*32 + lane];
            unsigned a0[4] = {A0.x, A0.y, A0.z, A0.w};
            unsigned a1[4] = {A1.x, A1.y, A1.z, A1.w};
            #pragma unroll
            for (int j = 0; j < 8; j++){
                uint2 Bv = Bs[((wnb+j)*4 + k8l)*32 + lane];
                unsigned b[2] = {Bv.x, Bv.y};
                mma_tf32(c[0][j], a0, b);
                mma_tf32(c[1][j], a1, b);
            }
        }
    }
}

// QKV GEMM -> g_q/g_k/g_v row-major (tf32 bits), q pre-scaled
__global__ __launch_bounds__(256) void qkv_mma(const float* __restrict__ bias){
    extern __shared__ uint4 sm4[];
    const int tid = threadIdx.x, lane = tid & 31, warp = tid >> 5;
    const int mb0 = blockIdx.x*8, nb0 = blockIdx.y*16;
    float c[2][8][4] = {};
    gemm_main(c, sm4, sm4 + 2048, g_xp, g_wqp, mb0, nb0, tid, lane, warp);

    const int m0 = mb0*16, n0 = nb0*8;
    #pragma unroll
    for (int j = 0; j < 8; j++){
        int n_abs = n0 + (warp&1)*64 + j*8;
        int which = n_abs / DMODEL;
        int rem = n_abs - which*DMODEL;
        int h = rem >> 6;
        int dh0 = (rem & 63) + 2*(lane&3);
        unsigned* dst = (which==0) ? g_q : (which==1 ? g_k : g_v);
        float sc = (which==0) ? SCALE : 1.0f;
        float b0 = bias[n_abs + 2*(lane&3)], b1 = bias[n_abs + 2*(lane&3) + 1];
        #pragma unroll
        for (int i = 0; i < 2; i++){
            int gm = m0 + ((warp>>1)*2 + i)*16 + (lane>>2);
            #pragma unroll
            for (int half = 0; half < 2; half++){
                int r = gm + half*8;
                int bb = r >> 11, nn = r & (NSEQ-1);
                unsigned* row = dst + ((size_t)((bb*NH + h)*NSEQ + nn))*DH + dh0;
                row[0] = f2t((c[i][j][half*2+0] + b0) * sc);
                row[1] = f2t((c[i][j][half*2+1] + b1) * sc);
            }
        }
    }
}

// Projection -> fp32 out
__global__ __launch_bounds__(256) void proj_mma(const float* __restrict__ bias,
                                                float* __restrict__ out){
    extern __shared__ uint4 sm4[];
    const int tid = threadIdx.x, lane = tid & 31, warp = tid >> 5;
    const int mb0 = blockIdx.x*8, nb0 = blockIdx.y*16;
    float c[2][8][4] = {};
    gemm_main(c, sm4, sm4 + 2048, g_ap, g_wpp, mb0, nb0, tid, lane, warp);

    const int m0 = mb0*16, n0 = nb0*8;
    #pragma unroll
    for (int j = 0; j < 8; j++){
        int gn = n0 + (warp&1)*64 + j*8 + 2*(lane&3);
        float b0 = bias[gn], b1 = bias[gn+1];
        #pragma unroll
        for (int i = 0; i < 2; i++){
            int gm = m0 + ((warp>>1)*2 + i)*16 + (lane>>2);
            #pragma unroll
            for (int half = 0; half < 2; half++){
                float* p = &out[(size_t)(gm + half*8)*DMODEL + gn];
                p[0] = c[i][j][half*2+0] + b0;
                p[1] = c[i][j][half*2+1] + b1;
            }
        }
    }
}

// ---------------------------------------------------------------------------
// Flash attention: R4 structure, packed-fragment Q/K/V smem (cp.async loads).
// smem: Qsp 32KB + Ksp 16KB + Vsp 16KB + Ps 34.8KB = 100352 B.
// ---------------------------------------------------------------------------
__global__ __launch_bounds__(256) void attn_mma(){
    extern __shared__ uint4 smq[];
    uint4* Qsp = smq;                       // [8 wblk][8 d8][32] uint4
    uint2* Ksp = (uint2*)(Qsp + 2048);      // [8 jb][8 d8][32]
    uint2* Vsp = Ksp + 2048;                // [8 vb][8 j][32]
    unsigned* Ps = (unsigned*)(Vsp + 2048); // [128][68]
    const int tid = threadIdx.x, lane = tid & 31, warp = tid >> 5;
    const int q0 = blockIdx.x * 128;
    const int bh = blockIdx.y;
    const int r0 = warp*16 + (lane>>2);

    {
        const uint4* Qg = g_qp + ((size_t)(bh*128) + (q0>>4))*256;
        #pragma unroll
        for (int l = 0; l < 8; l++)
            cp16(Qsp + tid + l*256, Qg + tid + l*256);
        CP_COMMIT();
    }
    const uint4* Kg4 = (const uint4*)(g_kp + (size_t)bh*65536);
    const uint4* Vg4 = (const uint4*)(g_vp + (size_t)bh*65536);

    float o[8][4] = {};
    float mi0 = -1e30f, mi1 = -1e30f, li0 = 0.f, li1 = 0.f;

    for (int t = 0; t < NSEQ/64; t++){
        __syncthreads();    // previous compute done reading Ksp/Vsp
        #pragma unroll
        for (int l = 0; l < 4; l++){
            cp16((uint4*)Ksp + tid + l*256, Kg4 + (size_t)t*1024 + tid + l*256);
            cp16((uint4*)Vsp + tid + l*256, Vg4 + (size_t)t*1024 + tid + l*256);
        }
        CP_COMMIT();
        CP_WAIT0();
        __syncthreads();    // tiles visible CTA-wide (Q included at t=0)

        // S = Q @ K^T  (Q pre-scaled)
        float s[8][4] = {};
        #pragma unroll
        for (int d8 = 0; d8 < 8; d8++){
            uint4 A = Qsp[(warp*8 + d8)*32 + lane];
            unsigned a[4] = {A.x, A.y, A.z, A.w};
            #pragma unroll
            for (int j = 0; j < 8; j++){
                uint2 Bv = Ksp[(j*8 + d8)*32 + lane];
                unsigned b[2] = {Bv.x, Bv.y};
                mma_tf32(s[j], a, b);
            }
        }

        // online softmax (quad shfl)
        float rm0 = -1e30f, rm1 = -1e30f;
        #pragma unroll
        for (int j = 0; j < 8; j++){
            rm0 = fmaxf(rm0, fmaxf(s[j][0], s[j][1]));
            rm1 = fmaxf(rm1, fmaxf(s[j][2], s[j][3]));
        }
        rm0 = fmaxf(rm0, __shfl_xor_sync(0xffffffffu, rm0, 1));
        rm0 = fmaxf(rm0, __shfl_xor_sync(0xffffffffu, rm0, 2));
        rm1 = fmaxf(rm1, __shfl_xor_sync(0xffffffffu, rm1, 1));
        rm1 = fmaxf(rm1, __shfl_xor_sync(0xffffffffu, rm1, 2));
        float mn0 = fmaxf(mi0, rm0), mn1 = fmaxf(mi1, rm1);
        float f0 = __expf(mi0 - mn0), f1 = __expf(mi1 - mn1);
        float sum0 = 0.f, sum1 = 0.f;
        #pragma unroll
        for (int j = 0; j < 8; j++){
            s[j][0] = __expf(s[j][0]-mn0); s[j][1] = __expf(s[j][1]-mn0);
            s[j][2] = __expf(s[j][2]-mn1); s[j][3] = __expf(s[j][3]-mn1);
            sum0 += s[j][0]+s[j][1];       sum1 += s[j][2]+s[j][3];
            o[j][0]*=f0; o[j][1]*=f0; o[j][2]*=f1; o[j][3]*=f1;
        }
        sum0 += __shfl_xor_sync(0xffffffffu, sum0, 1);
        sum0 += __shfl_xor_sync(0xffffffffu, sum0, 2);
        sum1 += __shfl_xor_sync(0xffffffffu, sum1, 1);
        sum1 += __shfl_xor_sync(0xffffffffu, sum1, 2);
        li0 = li0*f0 + sum0; li1 = li1*f1 + sum1;
        mi0 = mn0; mi1 = mn1;

        // P -> smem (warp-local rows)
        #pragma unroll
        for (int j = 0; j < 8; j++){
            int cc = j*8 + 2*(lane&3);
            *(uint2*)&Ps[r0*68 + cc]     = make_uint2(f2t(s[j][0]), f2t(s[j][1]));
            *(uint2*)&Ps[(r0+8)*68 + cc] = make_uint2(f2t(s[j][2]), f2t(s[j][3]));
        }
        __syncwarp();

        // O += P @ V
        #pragma unroll
        for (int kb = 0; kb < 8; kb++){
            int kn = kb*8;
            unsigned a[4];
            a[0] = Ps[r0*68     + kn + (lane&3)];
            a[1] = Ps[(r0+8)*68 + kn + (lane&3)];
            a[2] = Ps[r0*68     + kn + (lane&3) + 4];
            a[3] = Ps[(r0+8)*68 + kn + (lane&3) + 4];
            #pragma unroll
            for (int j = 0; j < 8; j++){
                uint2 Bv = Vsp[(kb*8 + j)*32 + lane];
                unsigned b[2] = {Bv.x, Bv.y};
                mma_tf32(o[j], a, b);
            }
        }
    }

    // epilogue -> g_att row-major
    const int b = bh / NH, h = bh % NH;
    float inv0 = 1.f/li0, inv1 = 1.f/li1;
    #pragma unroll
    for (int j = 0; j < 8; j++){
        int dh = j*8 + 2*(lane&3);
        int row0 = q0 + r0, row1 = row0 + 8;
        unsigned* p0 = g_att + ((size_t)(b*NSEQ + row0))*DMODEL + h*DH + dh;
        unsigned* p1 = g_att + ((size_t)(b*NSEQ + row1))*DMODEL + h*DH + dh;
        p0[0] = f2t(o[j][0]*inv0); p0[1] = f2t(o[j][1]*inv0);
        p1[0] = f2t(o[j][2]*inv1); p1[1] = f2t(o[j][3]*inv1);
    }
}

// ---------------------------------------------------------------------------
extern "C" void kernel_launch(void* const* d_in, const int* in_sizes, int n_in,
                              void* d_out, int out_size) {
    const float* x      = (const float*)d_in[0];
    const float* w_qkv  = (const float*)d_in[1];
    const float* b_qkv  = (const float*)d_in[2];
    const float* w_proj = (const float*)d_in[3];
    const float* b_proj = (const float*)d_in[4];
    float* out = (float*)d_out;

    const int attn_smem = 2048*16 + 2048*8 + 2048*8 + 128*68*4;   // 100352
    cudaFuncSetAttribute(attn_mma, cudaFuncAttributeMaxDynamicSharedMemorySize, attn_smem);
    cudaFuncSetAttribute(qkv_mma,  cudaFuncAttributeMaxDynamicSharedMemorySize, GEMM_SMEM2);
    cudaFuncSetAttribute(proj_mma, cudaFuncAttributeMaxDynamicSharedMemorySize, GEMM_SMEM2);

    x_pack  <<<3072, 256>>>(x);
    wq_pack <<<3456, 256>>>(w_qkv);
    wp_pack <<<1152, 256>>>(w_proj);
    qkv_mma <<<dim3(32, 18), 256, GEMM_SMEM2>>>(b_qkv);
    repack  <<<dim3(6144, 3), 256>>>();
    attn_mma<<<dim3(16, 24), 256, attn_smem>>>();
    att_pack<<<3072, 256>>>();
    proj_mma<<<dim3(32, 6),  256, GEMM_SMEM2>>>(b_proj, out);
}

// round 11
// speedup vs baseline: 1.7450x; 1.1159x over previous
#include <cuda_runtime.h>

#define NSEQ  2048
#define DMODEL 768
#define NH    12
#define DH    64
#define BATCH 2
#define MROWS 4096          // BATCH*NSEQ
#define S3DIM 2304          // 3*DMODEL
#define SCALE 0.125f
#define NBH   (BATCH*NH)    // 24
#define K8S   (DMODEL/8)    // 96

// Fragment-packed operands (tf32 bits)
__device__ uint4 g_xp [256*K8S*32];     // X A-frag   [mb][k8][lane]
__device__ uint2 g_wqp[288*K8S*32];     // Wqkv B-frag[nb][k8][lane]
__device__ uint2 g_wpp[ 96*K8S*32];     // Wproj B-frag
__device__ uint4 g_ap [256*K8S*32];     // attn-out A-frag
__device__ uint4 g_qp [NBH*128*8*32];   // Q A-frag  [bh][qb][d8][lane]
__device__ uint2 g_kp [NBH*256*8*32];   // K B-frag  [bh][jb][d8][lane]
__device__ uint2 g_vp [NBH*256*8*32];   // V B-frag  [bh][vb][j][lane]

__device__ __forceinline__ unsigned f2t(float f){
    unsigned u; asm("cvt.rna.tf32.f32 %0, %1;" : "=r"(u) : "f"(f)); return u;
}
__device__ __forceinline__ void mma_tf32(float c[4], const unsigned a[4], const unsigned b[2]){
    asm volatile("mma.sync.aligned.m16n8k8.row.col.f32.tf32.tf32.f32 "
        "{%0,%1,%2,%3}, {%4,%5,%6,%7}, {%8,%9}, {%0,%1,%2,%3};"
        : "+f"(c[0]), "+f"(c[1]), "+f"(c[2]), "+f"(c[3])
        : "r"(a[0]), "r"(a[1]), "r"(a[2]), "r"(a[3]), "r"(b[0]), "r"(b[1]));
}
__device__ __forceinline__ void cp16(void* sdst, const void* gsrc){
    unsigned sa = (unsigned)__cvta_generic_to_shared(sdst);
    asm volatile("cp.async.ca.shared.global [%0], [%1], 16;" :: "r"(sa), "l"(gsrc));
}
#define CP_COMMIT() asm volatile("cp.async.commit_group;")
#define CP_WAIT0()  asm volatile("cp.async.wait_group 0;")
#define FULL 0xffffffffu

// --- In-warp fragment layout exchanges (bit-exact permutations) ------------
// C-frag (u0,u1 rows q; u2,u3 rows q+8; cols 2m,2m+1) -> A-frag uint4
__device__ __forceinline__ uint4 xchg_A(unsigned u0, unsigned u1, unsigned u2, unsigned u3, int lane){
    int m = lane & 3, s0 = (lane & ~3) | (m >> 1), s1 = s0 + 2;
    unsigned a0l=__shfl_sync(FULL,u0,s0), a0h=__shfl_sync(FULL,u1,s0);
    unsigned a2l=__shfl_sync(FULL,u0,s1), a2h=__shfl_sync(FULL,u1,s1);
    unsigned a1l=__shfl_sync(FULL,u2,s0), a1h=__shfl_sync(FULL,u3,s0);
    unsigned a3l=__shfl_sync(FULL,u2,s1), a3h=__shfl_sync(FULL,u3,s1);
    return (m & 1) ? make_uint4(a0h,a1h,a2h,a3h) : make_uint4(a0l,a1l,a2l,a3l);
}
// C-frag rows q (u0,u1) -> K-style B-frag uint2 (cols k, k+4; same row group)
__device__ __forceinline__ uint2 xchg_B(unsigned u0, unsigned u1, int lane){
    int m = lane & 3, s0 = (lane & ~3) | (m >> 1), s1 = s0 + 2;
    unsigned lo0=__shfl_sync(FULL,u0,s0), lo1=__shfl_sync(FULL,u1,s0);
    unsigned hi0=__shfl_sync(FULL,u0,s1), hi1=__shfl_sync(FULL,u1,s1);
    return (m & 1) ? make_uint2(lo1,hi1) : make_uint2(lo0,hi0);
}
// C-frag rows 0..7 (u0,u1) -> transposed V-style B-frag uint2 (rows k,k+4; col q)
__device__ __forceinline__ uint2 xchg_Bt(unsigned u0, unsigned u1, int lane){
    int k = lane & 3, q = lane >> 2;
    int s0 = (k << 2) | (q >> 1), s1 = s0 + 16;
    unsigned a=__shfl_sync(FULL,u0,s0), b=__shfl_sync(FULL,u1,s0);
    unsigned c=__shfl_sync(FULL,u0,s1), d=__shfl_sync(FULL,u1,s1);
    return (q & 1) ? make_uint2(b,d) : make_uint2(a,c);
}

// ---------------------------------------------------------------------------
// Input pack kernels (fp32 GMEM -> tf32 fragment layouts)
// ---------------------------------------------------------------------------
__global__ __launch_bounds__(256) void x_pack(const float* __restrict__ X){
    int t = blockIdx.x*256 + threadIdx.x;
    int lane = t & 31, q = lane >> 2, k = lane & 3;
    int k8 = (t >> 5) % K8S, mb = (t >> 5) / K8S;
    int r = mb*16 + q, c = k8*8 + k;
    uint4 v;
    v.x = f2t(X[(size_t)r*DMODEL + c]);
    v.y = f2t(X[(size_t)(r+8)*DMODEL + c]);
    v.z = f2t(X[(size_t)r*DMODEL + c + 4]);
    v.w = f2t(X[(size_t)(r+8)*DMODEL + c + 4]);
    g_xp[t] = v;
}
__global__ __launch_bounds__(256) void wq_pack(const float* __restrict__ W){
    int t = blockIdx.x*256 + threadIdx.x;
    int lane = t & 31;
    int k8 = (t >> 5) % K8S, nb = (t >> 5) / K8S;
    int r = k8*8 + (lane & 3), c = nb*8 + (lane >> 2);
    g_wqp[t] = make_uint2(f2t(W[(size_t)r*S3DIM + c]), f2t(W[(size_t)(r+4)*S3DIM + c]));
}
__global__ __launch_bounds__(256) void wp_pack(const float* __restrict__ W){
    int t = blockIdx.x*256 + threadIdx.x;
    int lane = t & 31;
    int k8 = (t >> 5) % K8S, nb = (t >> 5) / K8S;
    int r = k8*8 + (lane & 3), c = nb*8 + (lane >> 2);
    g_wpp[t] = make_uint2(f2t(W[(size_t)r*DMODEL + c]), f2t(W[(size_t)(r+4)*DMODEL + c]));
}

// ---------------------------------------------------------------------------
// GEMM core (as R10): CTA 128x128, 8 warps, k-chunk 32, cp.async 2-stage.
// ---------------------------------------------------------------------------
#define GEMM_SMEM2 65536

__device__ __forceinline__ void gemm_load_chunk(uint4* Abuf, uint4* Bbuf4,
                                                const uint4* Aglob, const uint2* Bglob,
                                                int mb0, int nb0, int ch4, int tid){
    #pragma unroll
    for (int l = 0; l < 4; l++){
        int i = tid + l*256;
        int mbL = i >> 7, k8l = (i >> 5) & 3, ln = i & 31;
        cp16(Abuf + i, Aglob + ((size_t)(mb0+mbL)*K8S + ch4 + k8l)*32 + ln);
    }
    #pragma unroll
    for (int l = 0; l < 4; l++){
        int i = tid + l*256;
        int nbL = i >> 6, k8l = (i >> 4) & 3, u4 = i & 15;
        cp16(Bbuf4 + i, (const uint4*)(Bglob + ((size_t)(nb0+nbL)*K8S + ch4 + k8l)*32) + u4);
    }
}

__device__ __forceinline__ void gemm_main(float c[2][8][4], uint4* Asp, uint4* Bsp4,
                                          const uint4* Aglob, const uint2* Bglob,
                                          int mb0, int nb0, int tid, int lane, int warp){
    const int wmb = (warp >> 1)*2, wnb = (warp & 1)*8;
    gemm_load_chunk(Asp, Bsp4, Aglob, Bglob, mb0, nb0, 0, tid);
    CP_COMMIT();
    for (int ch = 0; ch < 24; ch++){
        CP_WAIT0();
        __syncthreads();
        if (ch + 1 < 24){
            gemm_load_chunk(Asp + ((ch+1)&1)*1024, Bsp4 + ((ch+1)&1)*1024,
                            Aglob, Bglob, mb0, nb0, (ch+1)*4, tid);
            CP_COMMIT();
        }
        const uint4* As = Asp + (ch&1)*1024;
        const uint2* Bs = (const uint2*)(Bsp4 + (ch&1)*1024);
        #pragma unroll
        for (int k8l = 0; k8l < 4; k8l++){
            uint4 A0 = As[((wmb+0)*4 + k8l)*32 + lane];
            uint4 A1 = As[((wmb+1)*4 + k8l)*32 + lane];
            unsigned a0[4] = {A0.x, A0.y, A0.z, A0.w};
            unsigned a1[4] = {A1.x, A1.y, A1.z, A1.w};
            #pragma unroll
            for (int j = 0; j < 8; j++){
                uint2 Bv = Bs[((wnb+j)*4 + k8l)*32 + lane];
                unsigned b[2] = {Bv.x, Bv.y};
                mma_tf32(c[0][j], a0, b);
                mma_tf32(c[1][j], a1, b);
            }
        }
    }
}

// ---------------------------------------------------------------------------
// QKV GEMM -> writes g_qp/g_kp/g_vp DIRECTLY in fragment layouts (shfl xchg)
// ---------------------------------------------------------------------------
__global__ __launch_bounds__(256) void qkv_mma(const float* __restrict__ bias){
    extern __shared__ uint4 sm4[];
    const int tid = threadIdx.x, lane = tid & 31, warp = tid >> 5;
    const int mb0 = blockIdx.x*8, nb0 = blockIdx.y*16;
    float c[2][8][4] = {};
    gemm_main(c, sm4, sm4 + 2048, g_xp, g_wqp, mb0, nb0, tid, lane, warp);

    const int m0 = mb0*16, n0 = nb0*8;
    #pragma unroll
    for (int j = 0; j < 8; j++){
        int n_abs = n0 + (warp&1)*64 + j*8;
        int which = n_abs / DMODEL;
        int rem = n_abs - which*DMODEL;
        int h = rem >> 6, d8 = (rem & 63) >> 3;
        float sc = (which==0) ? SCALE : 1.0f;
        float b0 = bias[n_abs + 2*(lane&3)], b1 = bias[n_abs + 2*(lane&3) + 1];
        #pragma unroll
        for (int i = 0; i < 2; i++){
            int gm = m0 + ((warp>>1)*2 + i)*16;      // 16-aligned row base
            int bb = gm >> 11, nnb = gm & (NSEQ-1);
            int bh = bb*NH + h;
            unsigned u0 = f2t((c[i][j][0] + b0) * sc);
            unsigned u1 = f2t((c[i][j][1] + b1) * sc);
            unsigned u2 = f2t((c[i][j][2] + b0) * sc);
            unsigned u3 = f2t((c[i][j][3] + b1) * sc);
            if (which == 0){            // Q: A-frag, 16-row block
                uint4 v = xchg_A(u0, u1, u2, u3, lane);
                g_qp[((size_t)(bh*128 + (nnb>>4))*8 + d8)*32 + lane] = v;
            } else if (which == 1){     // K: B-frag, two 8-row blocks
                int jb = nnb >> 3;
                g_kp[((size_t)(bh*256 + jb  )*8 + d8)*32 + lane] = xchg_B(u0, u1, lane);
                g_kp[((size_t)(bh*256 + jb+1)*8 + d8)*32 + lane] = xchg_B(u2, u3, lane);
            } else {                    // V: transposed B-frag, two 8-row blocks
                int vb = nnb >> 3;
                g_vp[((size_t)(bh*256 + vb  )*8 + d8)*32 + lane] = xchg_Bt(u0, u1, lane);
                g_vp[((size_t)(bh*256 + vb+1)*8 + d8)*32 + lane] = xchg_Bt(u2, u3, lane);
            }
        }
    }
}

// ---------------------------------------------------------------------------
// Flash attention: double-buffered K/V, P exchanged in registers (no Ps smem).
// smem: Q 32K + K 2x16K + V 2x16K = 96K -> 2 CTAs/SM.
// ---------------------------------------------------------------------------
#define ATTN_SMEM 98304

__global__ __launch_bounds__(256) void attn_mma(){
    extern __shared__ uint4 smq[];
    uint4* Qsp = smq;                       // [8 qb][8 d8][32]
    uint2* Kb  = (uint2*)(Qsp + 2048);      // [2][2048]
    uint2* Vb  = Kb + 2*2048;               // [2][2048]
    const int tid = threadIdx.x, lane = tid & 31, warp = tid >> 5;
    const int q0 = blockIdx.x * 128;
    const int bh = blockIdx.y;

    {   // prologue: Q tile + K/V tile 0, one group
        const uint4* Qg = g_qp + ((size_t)(bh*128) + (q0>>4))*256;
        #pragma unroll
        for (int l = 0; l < 8; l++) cp16(Qsp + tid + l*256, Qg + tid + l*256);
        const uint4* Kg4 = (const uint4*)(g_kp + (size_t)bh*65536);
        const uint4* Vg4 = (const uint4*)(g_vp + (size_t)bh*65536);
        #pragma unroll
        for (int l = 0; l < 4; l++){
            cp16((uint4*)Kb + tid + l*256, Kg4 + tid + l*256);
            cp16((uint4*)Vb + tid + l*256, Vg4 + tid + l*256);
        }
        CP_COMMIT();
    }
    const uint4* Kg4 = (const uint4*)(g_kp + (size_t)bh*65536);
    const uint4* Vg4 = (const uint4*)(g_vp + (size_t)bh*65536);

    float o[8][4] = {};
    float mi0 = -1e30f, mi1 = -1e30f, li0 = 0.f, li1 = 0.f;

    for (int t = 0; t < NSEQ/64; t++){
        CP_WAIT0();
        __syncthreads();   // tile t visible; all warps done with buf (t+1)&1
        if (t + 1 < NSEQ/64){
            uint4* kd = (uint4*)(Kb + ((t+1)&1)*2048);
            uint4* vd = (uint4*)(Vb + ((t+1)&1)*2048);
            #pragma unroll
            for (int l = 0; l < 4; l++){
                cp16(kd + tid + l*256, Kg4 + (size_t)(t+1)*1024 + tid + l*256);
                cp16(vd + tid + l*256, Vg4 + (size_t)(t+1)*1024 + tid + l*256);
            }
            CP_COMMIT();
        }
        const uint2* Ks = Kb + (t&1)*2048;
        const uint2* Vs = Vb + (t&1)*2048;

        // S = Q @ K^T  (Q pre-scaled)
        float s[8][4] = {};
        #pragma unroll
        for (int d8 = 0; d8 < 8; d8++){
            uint4 A = Qsp[(warp*8 + d8)*32 + lane];
            unsigned a[4] = {A.x, A.y, A.z, A.w};
            #pragma unroll
            for (int j = 0; j < 8; j++){
                uint2 Bv = Ks[(j*8 + d8)*32 + lane];
                unsigned b[2] = {Bv.x, Bv.y};
                mma_tf32(s[j], a, b);
            }
        }

        // online softmax (quad shfl)
        float rm0 = -1e30f, rm1 = -1e30f;
        #pragma unroll
        for (int j = 0; j < 8; j++){
            rm0 = fmaxf(rm0, fmaxf(s[j][0], s[j][1]));
            rm1 = fmaxf(rm1, fmaxf(s[j][2], s[j][3]));
        }
        rm0 = fmaxf(rm0, __shfl_xor_sync(FULL, rm0, 1));
        rm0 = fmaxf(rm0, __shfl_xor_sync(FULL, rm0, 2));
        rm1 = fmaxf(rm1, __shfl_xor_sync(FULL, rm1, 1));
        rm1 = fmaxf(rm1, __shfl_xor_sync(FULL, rm1, 2));
        float mn0 = fmaxf(mi0, rm0), mn1 = fmaxf(mi1, rm1);
        float f0 = __expf(mi0 - mn0), f1 = __expf(mi1 - mn1);
        float sum0 = 0.f, sum1 = 0.f;
        #pragma unroll
        for (int j = 0; j < 8; j++){
            s[j][0] = __expf(s[j][0]-mn0); s[j][1] = __expf(s[j][1]-mn0);
            s[j][2] = __expf(s[j][2]-mn1); s[j][3] = __expf(s[j][3]-mn1);
            sum0 += s[j][0]+s[j][1];       sum1 += s[j][2]+s[j][3];
            o[j][0]*=f0; o[j][1]*=f0; o[j][2]*=f1; o[j][3]*=f1;
        }
        sum0 += __shfl_xor_sync(FULL, sum0, 1);
        sum0 += __shfl_xor_sync(FULL, sum0, 2);
        sum1 += __shfl_xor_sync(FULL, sum1, 1);
        sum1 += __shfl_xor_sync(FULL, sum1, 2);
        li0 = li0*f0 + sum0; li1 = li1*f1 + sum1;
        mi0 = mn0; mi1 = mn1;

        // P: tf32 in registers
        unsigned up[8][4];
        #pragma unroll
        for (int j = 0; j < 8; j++){
            up[j][0] = f2t(s[j][0]); up[j][1] = f2t(s[j][1]);
            up[j][2] = f2t(s[j][2]); up[j][3] = f2t(s[j][3]);
        }

        // O += P @ V  (A-frag built by quad shuffle from C-frag P)
        #pragma unroll
        for (int kb = 0; kb < 8; kb++){
            uint4 Af = xchg_A(up[kb][0], up[kb][1], up[kb][2], up[kb][3], lane);
            unsigned a[4] = {Af.x, Af.y, Af.z, Af.w};
            #pragma unroll
            for (int j = 0; j < 8; j++){
                uint2 Bv = Vs[(kb*8 + j)*32 + lane];
                unsigned b[2] = {Bv.x, Bv.y};
                mma_tf32(o[j], a, b);
            }
        }
    }

    // epilogue -> g_ap directly in A-frag layout (coalesced uint4)
    const int b = bh / NH, h = bh % NH;
    const int mb = (b*NSEQ + q0 + warp*16) >> 4;
    float inv0 = 1.f/li0, inv1 = 1.f/li1;
    #pragma unroll
    for (int j = 0; j < 8; j++){
        unsigned u0 = f2t(o[j][0]*inv0), u1 = f2t(o[j][1]*inv0);
        unsigned u2 = f2t(o[j][2]*inv1), u3 = f2t(o[j][3]*inv1);
        uint4 v = xchg_A(u0, u1, u2, u3, lane);
        g_ap[((size_t)mb*K8S + h*8 + j)*32 + lane] = v;
    }
}

// ---------------------------------------------------------------------------
// Projection -> fp32 out
// ---------------------------------------------------------------------------
__global__ __launch_bounds__(256) void proj_mma(const float* __restrict__ bias,
                                                float* __restrict__ out){
    extern __shared__ uint4 sm4[];
    const int tid = threadIdx.x, lane = tid & 31, warp = tid >> 5;
    const int mb0 = blockIdx.x*8, nb0 = blockIdx.y*16;
    float c[2][8][4] = {};
    gemm_main(c, sm4, sm4 + 2048, g_ap, g_wpp, mb0, nb0, tid, lane, warp);

    const int m0 = mb0*16, n0 = nb0*8;
    #pragma unroll
    for (int j = 0; j < 8; j++){
        int gn = n0 + (warp&1)*64 + j*8 + 2*(lane&3);
        float b0 = bias[gn], b1 = bias[gn+1];
        #pragma unroll
        for (int i = 0; i < 2; i++){
            int gm = m0 + ((warp>>1)*2 + i)*16 + (lane>>2);
            #pragma unroll
            for (int half = 0; half < 2; half++){
                float* p = &out[(size_t)(gm + half*8)*DMODEL + gn];
                p[0] = c[i][j][half*2+0] + b0;
                p[1] = c[i][j][half*2+1] + b1;
            }
        }
    }
}

// ---------------------------------------------------------------------------
extern "C" void kernel_launch(void* const* d_in, const int* in_sizes, int n_in,
                              void* d_out, int out_size) {
    const float* x      = (const float*)d_in[0];
    const float* w_qkv  = (const float*)d_in[1];
    const float* b_qkv  = (const float*)d_in[2];
    const float* w_proj = (const float*)d_in[3];
    const float* b_proj = (const float*)d_in[4];
    float* out = (float*)d_out;

    cudaFuncSetAttribute(attn_mma, cudaFuncAttributeMaxDynamicSharedMemorySize, ATTN_SMEM);
    cudaFuncSetAttribute(qkv_mma,  cudaFuncAttributeMaxDynamicSharedMemorySize, GEMM_SMEM2);
    cudaFuncSetAttribute(proj_mma, cudaFuncAttributeMaxDynamicSharedMemorySize, GEMM_SMEM2);

    x_pack  <<<3072, 256>>>(x);
    wq_pack <<<3456, 256>>>(w_qkv);
    wp_pack <<<1152, 256>>>(w_proj);
    qkv_mma <<<dim3(32, 18), 256, GEMM_SMEM2>>>(b_qkv);
    attn_mma<<<dim3(16, 24), 256, ATTN_SMEM>>>();
    proj_mma<<<dim3(32, 6),  256, GEMM_SMEM2>>>(b_proj, out);
}

// round 17
// speedup vs baseline: 3.2940x; 1.8877x over previous
#include <cuda_runtime.h>
#include <cuda_fp16.h>

#define NSEQ  2048
#define DMODEL 768
#define NH    12
#define DH    64
#define BATCH 2
#define MROWS 4096
#define S3DIM 2304
#define SCALE 0.125f
#define NBH   (BATCH*NH)
#define K16S  (DMODEL/16)   // 48

// Fragment-packed fp16 operands
__device__ uint4 g_xp [256*K16S*32];    // X A-frag   [mb(16r)][k16][lane]
__device__ uint2 g_wqp[288*K16S*32];    // Wqkv B-frag[nb(8c)][k16][lane]
__device__ uint2 g_wpp[ 96*K16S*32];    // Wproj B-frag
__device__ uint4 g_ap [256*K16S*32];    // attn-out A-frag
__device__ uint4 g_qp [NBH*128*4*32];   // Q A-frag  [bh][qb(16r)][d16][lane]
__device__ uint2 g_kp [NBH*256*4*32];   // K B-frag  [bh][jb(8kv)][d16][lane]
__device__ uint2 g_vp [NBH*128*8*32];   // V B-frag  [bh][vb(16kv)][jdh][lane]

#define FULL 0xffffffffu

__device__ __forceinline__ unsigned ph2(float lo, float hi){
    __half2 h = __floats2half2_rn(lo, hi);   // .x = lo (low half), .y = hi
    return *(unsigned*)&h;
}
__device__ __forceinline__ void mma_f16(float c[4], const unsigned a[4], const unsigned b[2]){
    asm volatile("mma.sync.aligned.m16n8k16.row.col.f32.f16.f16.f32 "
        "{%0,%1,%2,%3}, {%4,%5,%6,%7}, {%8,%9}, {%0,%1,%2,%3};"
        : "+f"(c[0]), "+f"(c[1]), "+f"(c[2]), "+f"(c[3])
        : "r"(a[0]), "r"(a[1]), "r"(a[2]), "r"(a[3]), "r"(b[0]), "r"(b[1]));
}
__device__ __forceinline__ void cp16(void* sdst, const void* gsrc){
    unsigned sa = (unsigned)__cvta_generic_to_shared(sdst);
    asm volatile("cp.async.ca.shared.global [%0], [%1], 16;" :: "r"(sa), "l"(gsrc));
}
#define CP_COMMIT() asm volatile("cp.async.commit_group;")
#define CP_WAIT0()  asm volatile("cp.async.wait_group 0;")

// ---------------------------------------------------------------------------
// Input packs (fp32 -> fp16 fragment layouts)
// ---------------------------------------------------------------------------
__global__ __launch_bounds__(256) void x_pack(const float* __restrict__ X){
    int t = blockIdx.x*256 + threadIdx.x;          // 256*48*32
    int lane = t & 31, q = lane >> 2, k = lane & 3;
    int k16 = (t >> 5) % K16S, mb = (t >> 5) / K16S;
    int r = mb*16 + q, c = k16*16 + 2*k;
    const float* p0 = &X[(size_t)r*DMODEL + c];
    const float* p1 = &X[(size_t)(r+8)*DMODEL + c];
    uint4 v;
    v.x = ph2(p0[0], p0[1]);
    v.y = ph2(p1[0], p1[1]);
    v.z = ph2(p0[8], p0[9]);
    v.w = ph2(p1[8], p1[9]);
    g_xp[t] = v;
}
__global__ __launch_bounds__(256) void wq_pack(const float* __restrict__ W){
    int t = blockIdx.x*256 + threadIdx.x;          // 288*48*32
    int lane = t & 31;
    int k16 = (t >> 5) % K16S, nb = (t >> 5) / K16S;
    int kr = k16*16 + 2*(lane & 3), col = nb*8 + (lane >> 2);
    g_wqp[t] = make_uint2(
        ph2(W[(size_t)kr*S3DIM + col],     W[(size_t)(kr+1)*S3DIM + col]),
        ph2(W[(size_t)(kr+8)*S3DIM + col], W[(size_t)(kr+9)*S3DIM + col]));
}
__global__ __launch_bounds__(256) void wp_pack(const float* __restrict__ W){
    int t = blockIdx.x*256 + threadIdx.x;          // 96*48*32
    int lane = t & 31;
    int k16 = (t >> 5) % K16S, nb = (t >> 5) / K16S;
    int kr = k16*16 + 2*(lane & 3), col = nb*8 + (lane >> 2);
    g_wpp[t] = make_uint2(
        ph2(W[(size_t)kr*DMODEL + col],     W[(size_t)(kr+1)*DMODEL + col]),
        ph2(W[(size_t)(kr+8)*DMODEL + col], W[(size_t)(kr+9)*DMODEL + col]));
}

// ---------------------------------------------------------------------------
// GEMM core: CTA 128x128, 8 warps (4m x 2n), k-chunk 64 (4 k16), 2-stage.
// smem: A 2x16KB (uint4 frags) + B 2x16KB = 64KB.
// ---------------------------------------------------------------------------
#define GEMM_SMEM 65536

__device__ __forceinline__ void gemm_load_chunk(uint4* Abuf, uint4* Bbuf4,
                                                const uint4* Aglob, const uint2* Bglob,
                                                int mb0, int nb0, int ch4, int tid){
    #pragma unroll
    for (int l = 0; l < 4; l++){
        int i = tid + l*256;                       // A: 1024 uint4
        int mbL = i >> 7, k16l = (i >> 5) & 3, ln = i & 31;
        cp16(Abuf + i, Aglob + ((size_t)(mb0+mbL)*K16S + ch4 + k16l)*32 + ln);
    }
    #pragma unroll
    for (int l = 0; l < 4; l++){
        int i = tid + l*256;                       // B: 1024 uint4 (2048 uint2)
        int nbL = i >> 6, k16l = (i >> 4) & 3, u4 = i & 15;
        cp16(Bbuf4 + i, (const uint4*)(Bglob + ((size_t)(nb0+nbL)*K16S + ch4 + k16l)*32) + u4);
    }
}

__device__ __forceinline__ void gemm_main(float c[2][8][4], uint4* Asp, uint4* Bsp4,
                                          const uint4* Aglob, const uint2* Bglob,
                                          int mb0, int nb0, int tid, int lane, int warp){
    const int wmb = (warp >> 1)*2, wnb = (warp & 1)*8;
    gemm_load_chunk(Asp, Bsp4, Aglob, Bglob, mb0, nb0, 0, tid);
    CP_COMMIT();
    for (int ch = 0; ch < 12; ch++){
        CP_WAIT0();
        __syncthreads();
        if (ch + 1 < 12){
            gemm_load_chunk(Asp + ((ch+1)&1)*1024, Bsp4 + ((ch+1)&1)*1024,
                            Aglob, Bglob, mb0, nb0, (ch+1)*4, tid);
            CP_COMMIT();
        }
        const uint4* As = Asp + (ch&1)*1024;
        const uint2* Bs = (const uint2*)(Bsp4 + (ch&1)*1024);
        #pragma unroll
        for (int k16l = 0; k16l < 4; k16l++){
            uint4 A0 = As[((wmb+0)*4 + k16l)*32 + lane];
            uint4 A1 = As[((wmb+1)*4 + k16l)*32 + lane];
            unsigned a0[4] = {A0.x, A0.y, A0.z, A0.w};
            unsigned a1[4] = {A1.x, A1.y, A1.z, A1.w};
            #pragma unroll
            for (int j = 0; j < 8; j++){
                uint2 Bv = Bs[((wnb+j)*4 + k16l)*32 + lane];
                unsigned b[2] = {Bv.x, Bv.y};
                mma_f16(c[0][j], a0, b);
                mma_f16(c[1][j], a1, b);
            }
        }
    }
}

// ---------------------------------------------------------------------------
// QKV GEMM -> fragment-layout epilogues (Q/K identity pack, V 4-shfl transpose)
// ---------------------------------------------------------------------------
__global__ __launch_bounds__(256) void qkv_mma(const float* __restrict__ bias){
    extern __shared__ uint4 sm4[];
    const int tid = threadIdx.x, lane = tid & 31, warp = tid >> 5;
    const int mb0 = blockIdx.x*8, nb0 = blockIdx.y*16;
    float c[2][8][4] = {};
    gemm_main(c, sm4, sm4 + 2048, g_xp, g_wqp, mb0, nb0, tid, lane, warp);

    const int m0 = mb0*16;
    const int nwarp = nb0*8 + (warp&1)*64;        // 64-aligned -> single head
    const int which = nwarp / DMODEL;
    const int rem = nwarp - which*DMODEL;
    const int h = rem >> 6;
    const float sc = (which==0) ? SCALE : 1.0f;

    #pragma unroll
    for (int i = 0; i < 2; i++){
        int gm = m0 + ((warp>>1)*2 + i)*16;       // 16-aligned row base
        int bb = gm >> 11, nnb = gm & (NSEQ-1);
        int bh = bb*NH + h;
        // bias+scale into v[j][4]
        float v[8][4];
        #pragma unroll
        for (int j = 0; j < 8; j++){
            float b0 = bias[nwarp + j*8 + 2*(lane&3)];
            float b1 = bias[nwarp + j*8 + 2*(lane&3) + 1];
            v[j][0] = (c[i][j][0] + b0) * sc;
            v[j][1] = (c[i][j][1] + b1) * sc;
            v[j][2] = (c[i][j][2] + b0) * sc;
            v[j][3] = (c[i][j][3] + b1) * sc;
        }
        if (which == 0){            // Q: A-frag (identity pack)
            int qb = nnb >> 4;
            #pragma unroll
            for (int t = 0; t < 4; t++){
                uint4 f;
                f.x = ph2(v[2*t][0],   v[2*t][1]);
                f.y = ph2(v[2*t][2],   v[2*t][3]);
                f.z = ph2(v[2*t+1][0], v[2*t+1][1]);
                f.w = ph2(v[2*t+1][2], v[2*t+1][3]);
                g_qp[((size_t)(bh*128 + qb)*4 + t)*32 + lane] = f;
            }
        } else if (which == 1){     // K: B-frag (identity pack), two 8-row blocks
            int jb = nnb >> 3;
            #pragma unroll
            for (int t = 0; t < 4; t++){
                g_kp[((size_t)(bh*256 + jb  )*4 + t)*32 + lane] =
                    make_uint2(ph2(v[2*t][0], v[2*t][1]), ph2(v[2*t+1][0], v[2*t+1][1]));
                g_kp[((size_t)(bh*256 + jb+1)*4 + t)*32 + lane] =
                    make_uint2(ph2(v[2*t][2], v[2*t][3]), ph2(v[2*t+1][2], v[2*t+1][3]));
            }
        } else {                    // V: transposed B-frag (4 shfl per j)
            int vb = nnb >> 4;
            int k = lane & 3, g = lane >> 2;
            int s0 = 8*k + (g>>1), s1 = s0 + 4;
            int sel = g & 1;
            #pragma unroll
            for (int j = 0; j < 8; j++){
                unsigned h01 = ph2(v[j][0], v[j][1]);
                unsigned h23 = ph2(v[j][2], v[j][3]);
                unsigned u0 = __shfl_sync(FULL, h01, s0);
                unsigned u1 = __shfl_sync(FULL, h01, s1);
                unsigned u2 = __shfl_sync(FULL, h23, s0);
                unsigned u3 = __shfl_sync(FULL, h23, s1);
                unsigned e0 = sel ? (u0 >> 16) : (u0 & 0xffffu);
                unsigned e1 = sel ? (u1 >> 16) : (u1 & 0xffffu);
                unsigned e2 = sel ? (u2 >> 16) : (u2 & 0xffffu);
                unsigned e3 = sel ? (u3 >> 16) : (u3 & 0xffffu);
                g_vp[((size_t)(bh*128 + vb)*8 + j)*32 + lane] =
                    make_uint2(e0 | (e1 << 16), e2 | (e3 << 16));
            }
        }
    }
}

// ---------------------------------------------------------------------------
// Flash attention fp16: Q smem, K/V double-buffered, P identity-packed in regs.
// smem: Q 16K + K 2x8K + V 2x8K = 48KB.
// ---------------------------------------------------------------------------
#define ATTN_SMEM 49152

__global__ __launch_bounds__(256) void attn_mma(){
    extern __shared__ uint4 smq[];
    uint4* Qsp = smq;                       // [8 qb][4 d16][32]
    uint2* Kb  = (uint2*)(smq + 1024);      // [2][8 jb][4 d16][32]
    uint2* Vb  = Kb + 2*1024;               // [2][4 vb][8 jdh][32]
    const int tid = threadIdx.x, lane = tid & 31, warp = tid >> 5;
    const int q0 = blockIdx.x * 128;
    const int bh = blockIdx.y;

    {
        const uint4* Qg = g_qp + ((size_t)(bh*128) + (q0>>4))*128;   // 8 qb x 4 x 32
        #pragma unroll
        for (int l = 0; l < 4; l++) cp16(Qsp + tid + l*256, Qg + tid + l*256);
        const uint4* Kg4 = (const uint4*)(g_kp + (size_t)bh*32768);
        const uint4* Vg4 = (const uint4*)(g_vp + (size_t)bh*32768);
        #pragma unroll
        for (int l = 0; l < 2; l++){
            cp16((uint4*)Kb + tid + l*256, Kg4 + tid + l*256);
            cp16((uint4*)Vb + tid + l*256, Vg4 + tid + l*256);
        }
        CP_COMMIT();
    }
    const uint4* Kg4 = (const uint4*)(g_kp + (size_t)bh*32768);
    const uint4* Vg4 = (const uint4*)(g_vp + (size_t)bh*32768);

    float o[8][4] = {};
    float mi0 = -1e30f, mi1 = -1e30f, li0 = 0.f, li1 = 0.f;
    const int r0 = warp*16 + (lane>>2);

    for (int t = 0; t < NSEQ/64; t++){
        CP_WAIT0();
        __syncthreads();
        if (t + 1 < NSEQ/64){
            uint4* kd = (uint4*)(Kb + ((t+1)&1)*1024);
            uint4* vd = (uint4*)(Vb + ((t+1)&1)*1024);
            #pragma unroll
            for (int l = 0; l < 2; l++){
                cp16(kd + tid + l*256, Kg4 + (size_t)(t+1)*512 + tid + l*256);
                cp16(vd + tid + l*256, Vg4 + (size_t)(t+1)*512 + tid + l*256);
            }
            CP_COMMIT();
        }
        const uint2* Ks = Kb + (t&1)*1024;
        const uint2* Vs = Vb + (t&1)*1024;

        // S = Q @ K^T (Q pre-scaled)
        float s[8][4] = {};
        #pragma unroll
        for (int d16 = 0; d16 < 4; d16++){
            uint4 A = Qsp[(warp*4 + d16)*32 + lane];
            unsigned a[4] = {A.x, A.y, A.z, A.w};
            #pragma unroll
            for (int j = 0; j < 8; j++){
                uint2 Bv = Ks[(j*4 + d16)*32 + lane];
                unsigned b[2] = {Bv.x, Bv.y};
                mma_f16(s[j], a, b);
            }
        }

        // online softmax (quad shfl)
        float rm0 = -1e30f, rm1 = -1e30f;
        #pragma unroll
        for (int j = 0; j < 8; j++){
            rm0 = fmaxf(rm0, fmaxf(s[j][0], s[j][1]));
            rm1 = fmaxf(rm1, fmaxf(s[j][2], s[j][3]));
        }
        rm0 = fmaxf(rm0, __shfl_xor_sync(FULL, rm0, 1));
        rm0 = fmaxf(rm0, __shfl_xor_sync(FULL, rm0, 2));
        rm1 = fmaxf(rm1, __shfl_xor_sync(FULL, rm1, 1));
        rm1 = fmaxf(rm1, __shfl_xor_sync(FULL, rm1, 2));
        float mn0 = fmaxf(mi0, rm0), mn1 = fmaxf(mi1, rm1);
        float f0 = __expf(mi0 - mn0), f1 = __expf(mi1 - mn1);
        float sum0 = 0.f, sum1 = 0.f;
        #pragma unroll
        for (int j = 0; j < 8; j++){
            s[j][0] = __expf(s[j][0]-mn0); s[j][1] = __expf(s[j][1]-mn0);
            s[j][2] = __expf(s[j][2]-mn1); s[j][3] = __expf(s[j][3]-mn1);
            sum0 += s[j][0]+s[j][1];       sum1 += s[j][2]+s[j][3];
            o[j][0]*=f0; o[j][1]*=f0; o[j][2]*=f1; o[j][3]*=f1;
        }
        sum0 += __shfl_xor_sync(FULL, sum0, 1);
        sum0 += __shfl_xor_sync(FULL, sum0, 2);
        sum1 += __shfl_xor_sync(FULL, sum1, 1);
        sum1 += __shfl_xor_sync(FULL, sum1, 2);
        li0 = li0*f0 + sum0; li1 = li1*f1 + sum1;
        mi0 = mn0; mi1 = mn1;

        // P -> fp16 A-frags (identity pack, zero shuffles)
        unsigned pa[4][4];
        #pragma unroll
        for (int kb = 0; kb < 4; kb++){
            pa[kb][0] = ph2(s[2*kb][0],   s[2*kb][1]);
            pa[kb][1] = ph2(s[2*kb][2],   s[2*kb][3]);
            pa[kb][2] = ph2(s[2*kb+1][0], s[2*kb+1][1]);
            pa[kb][3] = ph2(s[2*kb+1][2], s[2*kb+1][3]);
        }

        // O += P @ V
        #pragma unroll
        for (int kb = 0; kb < 4; kb++){
            #pragma unroll
            for (int j = 0; j < 8; j++){
                uint2 Bv = Vs[(kb*8 + j)*32 + lane];
                unsigned b[2] = {Bv.x, Bv.y};
                mma_f16(o[j], pa[kb], b);
            }
        }
    }

    // epilogue -> g_ap A-frags (identity pack)
    const int b = bh / NH, h = bh % NH;
    const int mb = (b*NSEQ + q0 + warp*16) >> 4;
    float inv0 = 1.f/li0, inv1 = 1.f/li1;
    #pragma unroll
    for (int t4 = 0; t4 < 4; t4++){
        uint4 f;
        f.x = ph2(o[2*t4][0]*inv0,   o[2*t4][1]*inv0);
        f.y = ph2(o[2*t4][2]*inv1,   o[2*t4][3]*inv1);
        f.z = ph2(o[2*t4+1][0]*inv0, o[2*t4+1][1]*inv0);
        f.w = ph2(o[2*t4+1][2]*inv1, o[2*t4+1][3]*inv1);
        g_ap[((size_t)mb*K16S + h*4 + t4)*32 + lane] = f;
    }
    (void)r0;
}

// ---------------------------------------------------------------------------
// Projection -> fp32 out
// ---------------------------------------------------------------------------
__global__ __launch_bounds__(256) void proj_mma(const float* __restrict__ bias,
                                                float* __restrict__ out){
    extern __shared__ uint4 sm4[];
    const int tid = threadIdx.x, lane = tid & 31, warp = tid >> 5;
    const int mb0 = blockIdx.x*8, nb0 = blockIdx.y*16;
    float c[2][8][4] = {};
    gemm_main(c, sm4, sm4 + 2048, g_ap, g_wpp, mb0, nb0, tid, lane, warp);

    const int m0 = mb0*16, n0 = nb0*8;
    #pragma unroll
    for (int j = 0; j < 8; j++){
        int gn = n0 + (warp&1)*64 + j*8 + 2*(lane&3);
        float b0 = bias[gn], b1 = bias[gn+1];
        #pragma unroll
        for (int i = 0; i < 2; i++){
            int gm = m0 + ((warp>>1)*2 + i)*16 + (lane>>2);
            #pragma unroll
            for (int half = 0; half < 2; half++){
                float* p = &out[(size_t)(gm + half*8)*DMODEL + gn];
                p[0] = c[i][j][half*2+0] + b0;
                p[1] = c[i][j][half*2+1] + b1;
            }
        }
    }
}

// ---------------------------------------------------------------------------
extern "C" void kernel_launch(void* const* d_in, const int* in_sizes, int n_in,
                              void* d_out, int out_size) {
    const float* x      = (const float*)d_in[0];
    const float* w_qkv  = (const float*)d_in[1];
    const float* b_qkv  = (const float*)d_in[2];
    const float* w_proj = (const float*)d_in[3];
    const float* b_proj = (const float*)d_in[4];
    float* out = (float*)d_out;

    cudaFuncSetAttribute(attn_mma, cudaFuncAttributeMaxDynamicSharedMemorySize, ATTN_SMEM);
    cudaFuncSetAttribute(qkv_mma,  cudaFuncAttributeMaxDynamicSharedMemorySize, GEMM_SMEM);
    cudaFuncSetAttribute(proj_mma, cudaFuncAttributeMaxDynamicSharedMemorySize, GEMM_SMEM);

    x_pack  <<<1536, 256>>>(x);
    wq_pack <<<1728, 256>>>(w_qkv);
    wp_pack <<< 576, 256>>>(w_proj);
    qkv_mma <<<dim3(32, 18), 256, GEMM_SMEM>>>(b_qkv);
    attn_mma<<<dim3(16, 24), 256, ATTN_SMEM>>>();
    proj_mma<<<dim3(32, 6),  256, GEMM_SMEM>>>(b_proj, out);
}